// round 15
// baseline (speedup 1.0000x reference)
#include <cuda_runtime.h>

#define T_STEPS 256
#define NPRE    1024
#define NPOST   1024
#define K       16            // 2^-16 rel truncation; measured rel_err 3.2e-5, 30x under 1e-3

// Scratch vectors (no allocations allowed)
__device__ float g_x[NPRE];   // pre trace at T
__device__ float g_p[NPRE];   // pre[T-1][:]
__device__ float g_y[NPOST];  // post trace at T
__device__ float g_q[NPOST];  // post[T-1][:]

// Kernel A: closed-form traces, computed ONCE.
// x[i] = sum_k pre[T-K+k][i] * 2^(k-K)  (TE=1 wipes e history; TP=TN=2 geometric)
__global__ void trace_kernel(const float* __restrict__ pre,
                             const float* __restrict__ post) {
    const int t     = blockIdx.x * blockDim.x + threadIdx.x;  // 0..2047
    const int which = t >> 10;                                // 0 = pre, 1 = post
    const int col   = t & 1023;

    const float* __restrict__ s = which ? post : pre;
    const float* __restrict__ b = s + (size_t)(T_STEPS - K) * NPRE + col;

    float a0 = 0.0f, a1 = 0.0f, last = 0.0f;
    #pragma unroll
    for (int k = 0; k < K; k += 2) {              // 16 independent loads, MLP=16
        const float v0 = b[(size_t)(k + 0) * NPRE];
        const float v1 = b[(size_t)(k + 1) * NPRE];
        a0 = fmaf(v0, __uint_as_float((unsigned)(127 - K + k + 0) << 23), a0);
        a1 = fmaf(v1, __uint_as_float((unsigned)(127 - K + k + 1) << 23), a1);
        last = v1;                                // k+1 == K-1 survives
    }
    const float acc = a0 + a1;

    if (which) { g_y[col] = acc; g_q[col] = last; }
    else       { g_x[col] = acc; g_p[col] = last; }
}

// Kernel B: e[i][j] = x[i]*q[j] - p[i]*y[j].
// 64 CTAs x 1024 threads, 4 rows per thread (4x fewer threads than R12):
// y4/q4 loaded once, reused 4x; 4 broadcast x/p scalars prefetched; 4 STG.128.
__global__ __launch_bounds__(1024, 2)
void outer_kernel(float* __restrict__ e) {
    const int tid   = threadIdx.x;
    const int col4  = tid & 255;                  // float4 column group
    const int rquad = tid >> 8;                   // 0..3
    const int i0    = blockIdx.x * 16 + rquad * 4; // 16 rows per CTA

    const float4 y4 = reinterpret_cast<const float4*>(g_y)[col4];
    const float4 q4 = reinterpret_cast<const float4*>(g_q)[col4];

    // Prefetch the 4 row scalars together (MLP=8, all broadcast loads)
    float xi[4], pi[4];
    #pragma unroll
    for (int rr = 0; rr < 4; rr++) {
        xi[rr] = g_x[i0 + rr];
        pi[rr] = g_p[i0 + rr];
    }

    float4* __restrict__ out4 = reinterpret_cast<float4*>(e);
    #pragma unroll
    for (int rr = 0; rr < 4; rr++) {
        float4 o;
        o.x = fmaf(xi[rr], q4.x, -pi[rr] * y4.x);
        o.y = fmaf(xi[rr], q4.y, -pi[rr] * y4.y);
        o.z = fmaf(xi[rr], q4.z, -pi[rr] * y4.z);
        o.w = fmaf(xi[rr], q4.w, -pi[rr] * y4.w);
        out4[(size_t)(i0 + rr) * (NPOST / 4) + col4] = o;
    }
}

extern "C" void kernel_launch(void* const* d_in, const int* in_sizes, int n_in,
                              void* d_out, int out_size) {
    const float* pre  = (const float*)d_in[0];   // [T, NPRE]
    const float* post = (const float*)d_in[1];   // [T, NPOST]
    float* e = (float*)d_out;                    // [NPRE, NPOST]

    trace_kernel<<<8, 256>>>(pre, post);
    outer_kernel<<<NPRE / 16, 1024>>>(e);        // 64 CTAs
}

// round 16
// speedup vs baseline: 1.3478x; 1.3478x over previous
#include <cuda_runtime.h>

#define T_STEPS 256
#define NPRE    1024
#define NPOST   1024
#define K       16     // 2^-16 rel truncation; measured rel_err 3.2e-5, 30x under 1e-3
#define TI      64     // rows per CTA tile
#define TJ      128    // cols per CTA tile
#define NTHR    1024

// Single launch, 2-D tiled: CTA (bx,by) owns rows [by*64,..) x cols [bx*128,..).
// Per-CTA trace work = K*(64+128) = 3072 loads (5.3x less than full-y recompute).
// e[i][j] = x[i]*q_last[j] - p_last[i]*y[j];  x = sum_k pre[T-K+k][i] * 2^(k-K)
__global__ __launch_bounds__(NTHR, 1)
void stdp_tiled_kernel(const float* __restrict__ pre,
                       const float* __restrict__ post,
                       float* __restrict__ e) {
    __shared__ float s_ypart[4][TJ];  // per-k-quarter partial y
    __shared__ float s_q[TJ];         // post[T-1][tile cols]
    __shared__ float s_x[TI];         // x trace, tile rows
    __shared__ float s_p[TI];         // pre[T-1][tile rows]

    const int tid = threadIdx.x;
    const int j0  = blockIdx.x * TJ;  // col-tile origin
    const int i0  = blockIdx.y * TI;  // row-tile origin

    if (tid < 512) {
        // ---- Phase A-y (warps 0..15): col = tid&127, k-quarter = tid>>7 ----
        const int col = tid & 127;
        const int kq  = tid >> 7;
        const float* __restrict__ b =
            post + (size_t)(T_STEPS - K + kq * 4) * NPOST + j0 + col;
        const float v0 = b[0 * NPOST];
        const float v1 = b[1 * NPOST];
        const float v2 = b[2 * NPOST];
        const float v3 = b[3 * NPOST];
        // weight(k)=2^(k-16)=2^(4kq-16)*{1,2,4,8}; exact exponent-bit ldexp
        const float wb = __uint_as_float((unsigned)(127 - K + 4 * kq) << 23);
        s_ypart[kq][col] = wb * fmaf(8.0f, v3, fmaf(4.0f, v2, fmaf(2.0f, v1, v0)));
        if (kq == 3) s_q[col] = v3;                     // k = 15 doubles as q_last
    } else {
        // ---- Phase A-x (warps 16..31): row r = u>>3, k-slot sub = u&7 ----
        const int u   = tid - 512;
        const int r   = u >> 3;                         // 0..63
        const int sub = u & 7;                          // handles k=sub and k=sub+8
        const float va = pre[(size_t)(T_STEPS - K + sub)     * NPRE + i0 + r];
        const float vb = pre[(size_t)(T_STEPS - K + sub + 8) * NPRE + i0 + r];
        // va*2^(sub-16) + vb*2^(sub-8) = 2^(sub-16)*(va + 256*vb)
        float v = fmaf(256.0f, vb, va)
                  * __uint_as_float((unsigned)(127 - K + sub) << 23);
        // reduce across the 8 contiguous lanes owning this row
        #pragma unroll
        for (int o = 4; o; o >>= 1) v += __shfl_xor_sync(0xFFFFFFFFu, v, o);
        if (sub == 0) s_x[r] = v;
        if (sub == 7) s_p[r] = vb;                      // k = 15 is p_last
    }

    __syncthreads();

    // ---- Phase C: thread -> (2 rows, 4 cols). col4 local 0..31, rpair 0..31 ----
    const int col4  = tid & 31;
    const int rpair = tid >> 5;

    const float4 p0 = reinterpret_cast<const float4*>(s_ypart[0])[col4];
    const float4 p1 = reinterpret_cast<const float4*>(s_ypart[1])[col4];
    const float4 p2 = reinterpret_cast<const float4*>(s_ypart[2])[col4];
    const float4 p3 = reinterpret_cast<const float4*>(s_ypart[3])[col4];
    const float4 q4 = reinterpret_cast<const float4*>(s_q)[col4];

    float4 y4;
    y4.x = (p0.x + p1.x) + (p2.x + p3.x);
    y4.y = (p0.y + p1.y) + (p2.y + p3.y);
    y4.z = (p0.z + p1.z) + (p2.z + p3.z);
    y4.w = (p0.w + p1.w) + (p2.w + p3.w);

    float4* __restrict__ out4 =
        reinterpret_cast<float4*>(e) + (size_t)(j0 / 4) + col4;

    #pragma unroll
    for (int rr = 0; rr < 2; rr++) {
        const int r = rpair * 2 + rr;
        const float xi = s_x[r];
        const float pi = s_p[r];
        float4 o;
        o.x = fmaf(xi, q4.x, -pi * y4.x);
        o.y = fmaf(xi, q4.y, -pi * y4.y);
        o.z = fmaf(xi, q4.z, -pi * y4.z);
        o.w = fmaf(xi, q4.w, -pi * y4.w);
        out4[(size_t)(i0 + r) * (NPOST / 4)] = o;
    }
}

extern "C" void kernel_launch(void* const* d_in, const int* in_sizes, int n_in,
                              void* d_out, int out_size) {
    const float* pre  = (const float*)d_in[0];   // [T, NPRE]
    const float* post = (const float*)d_in[1];   // [T, NPOST]
    float* e = (float*)d_out;                    // [NPRE, NPOST]

    dim3 grid(NPOST / TJ, NPRE / TI);            // (8, 16) = 128 CTAs, one wave
    stdp_tiled_kernel<<<grid, NTHR>>>(pre, post, e);
}